// round 2
// baseline (speedup 1.0000x reference)
#include <cuda_runtime.h>
#include <math.h>

#define Bsz   4096
#define Lh    64
#define Dh    16
#define Hh    128
#define ROWS  32
#define THREADS 512
#define CTAS  128
#define HEAD_IN 144
#define OUTD  60

struct SM {
    float h[2][ROWS][Hh];    // 32 KB  hidden state per layer
    float c[2][ROWS][Hh];    // 32 KB  cell state per layer
    float xin[ROWS][Hh];     // 16 KB  projected input x_t
    float ht[ROWS][Hh];      // 16 KB  h_tilde scratch
    float sv[ROWS][Hh];      // 16 KB  saved encoded state at t=last
    float wp[Dh][Hh];        // 8 KB   Wp cached
    float histb[ROWS][Dh];   // 2 KB   history row slice at t
    float msk[ROWS];
    float dec[ROWS];
    int   last[ROWS];
};

__device__ __forceinline__ float sigf(float x) {
    return 1.0f / (1.0f + expf(-x));
}

__device__ __forceinline__ float fixv(float x) {
    if (!(x == x)) return 0.0f;          // NaN
    if (x > 1e38f) return 1e4f;          // +inf
    if (x < -1e38f) return -1e4f;        // -inf
    return x;
}

__global__ void __launch_bounds__(THREADS, 1)
tlstm_kernel(const float* __restrict__ history, const float* __restrict__ hmask,
             const float* __restrict__ Wp,  const float* __restrict__ bp,
             const float* __restrict__ Wx,  const float* __restrict__ bx,
             const float* __restrict__ Uh,  const float* __restrict__ Wd,
             const float* __restrict__ bd,  const float* __restrict__ Wt,
             const float* __restrict__ bt,  const float* __restrict__ ln_g,
             const float* __restrict__ ln_b, const float* __restrict__ W1,
             const float* __restrict__ b1,  const float* __restrict__ W2,
             const float* __restrict__ b2,  float* __restrict__ out)
{
    extern __shared__ char smraw[];
    SM* sm = reinterpret_cast<SM*>(smraw);

    const int tid  = threadIdx.x;
    const int b0   = blockIdx.x * ROWS;
    const int w    = tid >> 5;
    const int lane = tid & 31;
    const int wk   = w & 7;          // k-warp  (8 warps along k)
    const int wr   = w >> 3;         // row-warp (2 groups of 16 rows)
    const int half = lane >> 4;
    const int kk   = lane & 15;
    const int k    = wk * 16 + kk;   // this thread's output channel
    const int rb   = wr * 16 + half * 8;  // first of this thread's 8 rows

    // ---- init: zero states, cache Wp, compute last index per row ----
    for (int i = tid; i < 2 * ROWS * Hh; i += THREADS) {
        (&sm->h[0][0][0])[i] = 0.0f;
        (&sm->c[0][0][0])[i] = 0.0f;
    }
    for (int i = tid; i < Dh * Hh; i += THREADS)
        (&sm->wp[0][0])[i] = Wp[i];
    if (tid < ROWS) {
        const float* mp = hmask + (size_t)(b0 + tid) * Lh;
        float s = 0.0f;
        for (int t = 0; t < Lh; t++) s += mp[t];
        s = fminf(fmaxf(s, 1.0f), (float)Lh);
        sm->last[tid] = (int)s - 1;
    }
    __syncthreads();

    // ---- per-k constants in registers ----
    const float bpk  = bp[k];
    const float bxi0 = bx[(0*4+1)*Hh + k], bxo0 = bx[(0*4+2)*Hh + k], bxc0 = bx[(0*4+3)*Hh + k];
    const float bxi1 = bx[(1*4+1)*Hh + k], bxo1 = bx[(1*4+2)*Hh + k], bxc1 = bx[(1*4+3)*Hh + k];
    const float bd0  = bd[k],      bd1 = bd[Hh + k];
    const float wt0  = Wt[k],      wt1 = Wt[Hh + k];
    const float bt0  = bt[k],      bt1 = bt[Hh + k];

    // ================= time loop =================
    for (int t = 0; t < Lh; t++) {
        // stage history slice + mask
        {
            int r = tid >> 4, d = tid & 15;
            sm->histb[r][d] = history[((size_t)(b0 + r) * Lh + t) * Dh + d];
            if (tid < ROWS)
                sm->msk[tid] = hmask[(size_t)(b0 + tid) * Lh + t];
        }
        __syncthreads();

        if (tid < ROWS) {
            float dd = fmaxf(sm->histb[tid][5], 0.0f);
            sm->dec[tid] = 1.0f / logf(2.718281828459045f + dd);
        }
        // x_t = hist @ Wp + bp   (D=16 inner dim, tiny)
        {
            float acc[8];
            #pragma unroll
            for (int rr = 0; rr < 8; rr++) acc[rr] = bpk;
            #pragma unroll
            for (int d = 0; d < Dh; d++) {
                float wv = sm->wp[d][k];
                #pragma unroll
                for (int rr = 0; rr < 8; rr++)
                    acc[rr] += sm->histb[rb + rr][d] * wv;
            }
            #pragma unroll
            for (int rr = 0; rr < 8; rr++) sm->xin[rb + rr][k] = acc[rr];
        }
        __syncthreads();

        // ---- two LSTM-variant layers ----
        #pragma unroll
        for (int l = 0; l < 2; l++) {
            const float* inp  = (l == 0) ? &sm->xin[0][0] : &sm->h[0][0][0];
            float*       hcur = &sm->h[l][0][0];
            const float* pWxi = Wx + ((size_t)(l*4+1) * Hh) * Hh + k;
            const float* pWxo = Wx + ((size_t)(l*4+2) * Hh) * Hh + k;
            const float* pWxc = Wx + ((size_t)(l*4+3) * Hh) * Hh + k;
            const float* pUhi = Uh + ((size_t)(l*4+1) * Hh) * Hh + k;
            const float* pUho = Uh + ((size_t)(l*4+2) * Hh) * Hh + k;
            const float* pUhc = Uh + ((size_t)(l*4+3) * Hh) * Hh + k;

            float zi[8], zo[8], zc[8];
            const float bi = l ? bxi1 : bxi0;
            const float bo = l ? bxo1 : bxo0;
            const float bc = l ? bxc1 : bxc0;
            #pragma unroll
            for (int rr = 0; rr < 8; rr++) { zi[rr] = bi; zo[rr] = bo; zc[rr] = bc; }

            // gate GEMV: 6 weight streams, 8-row register blocking
            for (int j = 0; j < Hh; j += 4) {
                const int jo = j * Hh;
                float wxi[4], wxo[4], wxc[4], ui[4], uo[4], uc[4];
                #pragma unroll
                for (int u = 0; u < 4; u++) {
                    wxi[u] = pWxi[jo + u*Hh]; wxo[u] = pWxo[jo + u*Hh]; wxc[u] = pWxc[jo + u*Hh];
                    ui[u]  = pUhi[jo + u*Hh]; uo[u]  = pUho[jo + u*Hh]; uc[u]  = pUhc[jo + u*Hh];
                }
                #pragma unroll
                for (int rr = 0; rr < 8; rr++) {
                    const int r = rb + rr;
                    float4 x4 = *reinterpret_cast<const float4*>(inp  + r*Hh + j);
                    float4 h4 = *reinterpret_cast<const float4*>(hcur + r*Hh + j);
                    zi[rr] += x4.x*wxi[0] + x4.y*wxi[1] + x4.z*wxi[2] + x4.w*wxi[3]
                            + h4.x*ui[0]  + h4.y*ui[1]  + h4.z*ui[2]  + h4.w*ui[3];
                    zo[rr] += x4.x*wxo[0] + x4.y*wxo[1] + x4.z*wxo[2] + x4.w*wxo[3]
                            + h4.x*uo[0]  + h4.y*uo[1]  + h4.z*uo[2]  + h4.w*uo[3];
                    zc[rr] += x4.x*wxc[0] + x4.y*wxc[1] + x4.z*wxc[2] + x4.w*wxc[3]
                            + h4.x*uc[0]  + h4.y*uc[1]  + h4.z*uc[2]  + h4.w*uc[3];
                }
            }

            // epilogue 1: gates -> h_tilde (note: f gate is dead code in reference)
            float ot[8], htl[8];
            #pragma unroll
            for (int rr = 0; rr < 8; rr++) {
                float it = sigf(zi[rr]);
                ot[rr]   = sigf(zo[rr]);
                float ct = tanhf(zc[rr]);
                htl[rr]  = ct + it;
                sm->ht[rb + rr][k] = htl[rr];
            }
            __syncthreads();

            // h_short = tanh(h_tilde @ Wd + bd)
            const float* pWd = Wd + (size_t)l * Hh * Hh + k;
            const float  bdl = l ? bd1 : bd0;
            float hsv[8];
            #pragma unroll
            for (int rr = 0; rr < 8; rr++) hsv[rr] = bdl;
            for (int j = 0; j < Hh; j += 4) {
                const int jo = j * Hh;
                float wd0 = pWd[jo], wd1 = pWd[jo + Hh], wd2 = pWd[jo + 2*Hh], wd3 = pWd[jo + 3*Hh];
                #pragma unroll
                for (int rr = 0; rr < 8; rr++) {
                    float4 t4 = *reinterpret_cast<const float4*>(&sm->ht[rb + rr][j]);
                    hsv[rr] += t4.x*wd0 + t4.y*wd1 + t4.z*wd2 + t4.w*wd3;
                }
            }

            const float wtl = l ? wt1 : wt0;
            const float btl = l ? bt1 : bt0;
            #pragma unroll
            for (int rr = 0; rr < 8; rr++) {
                const int r = rb + rr;
                float hs    = tanhf(hsv[rr]);
                float dt    = sigf(sm->dec[r] * wtl + btl);
                float hstar = (htl[rr] - hs) + hs * dt;
                float cold  = sm->c[l][r][k];
                float cn    = tanhf(hstar + ot[rr] * cold);
                float hn    = ot[rr] * tanhf(cn);
                float m     = sm->msk[r];
                float hv    = m * hn + (1.0f - m) * hcur[r*Hh + k];
                float cv    = m * cn + (1.0f - m) * cold;
                sm->c[l][r][k] = cv;
                hcur[r*Hh + k] = hv;
                if (l == 1 && t == sm->last[r])
                    sm->sv[r][k] = m * hv;   // encoded = outs * mask
            }
            __syncthreads();
        }
    }

    // ================= forecast head =================
    // gather last-valid observation into histb
    {
        int r = tid >> 4, d = tid & 15;
        sm->histb[r][d] = history[((size_t)(b0 + r) * Lh + sm->last[r]) * Dh + d];
    }
    __syncthreads();

    const unsigned FULL = 0xffffffffu;
    #pragma unroll
    for (int rr = 0; rr < 2; rr++) {
        const int r = w * 2 + rr;

        // LayerNorm stats over state[144] = [hist16 | encoded128]
        float s = 0.0f, s2 = 0.0f;
        for (int i = lane; i < HEAD_IN; i += 32) {
            float v = (i < 16) ? sm->histb[r][i] : sm->sv[r][i - 16];
            s += v; s2 += v * v;
        }
        #pragma unroll
        for (int off = 16; off; off >>= 1) {
            s  += __shfl_xor_sync(FULL, s,  off);
            s2 += __shfl_xor_sync(FULL, s2, off);
        }
        float mean = s / (float)HEAD_IN;
        float var  = s2 / (float)HEAD_IN - mean * mean;
        float rstd = rsqrtf(var + 1e-5f);

        // y1 = relu(sn @ W1 + b1), lane owns 4 consecutive j
        const int j0 = lane * 4;
        float4 acc = *reinterpret_cast<const float4*>(b1 + j0);
        for (int i = 0; i < HEAD_IN; i++) {
            float v  = (i < 16) ? sm->histb[r][i] : sm->sv[r][i - 16];
            float sn = (v - mean) * rstd * ln_g[i] + ln_b[i];
            float4 w4 = *reinterpret_cast<const float4*>(W1 + i * Hh + j0);
            acc.x += sn * w4.x; acc.y += sn * w4.y;
            acc.z += sn * w4.z; acc.w += sn * w4.w;
        }
        float y[4] = { fmaxf(acc.x, 0.0f), fmaxf(acc.y, 0.0f),
                       fmaxf(acc.z, 0.0f), fmaxf(acc.w, 0.0f) };

        // out = y1 @ W2 + b2 via warp shuffle of y1
        const int o0 = lane, o1 = lane + 32;
        float a0 = b2[o0];
        float a1 = (o1 < OUTD) ? b2[o1] : 0.0f;
        #pragma unroll
        for (int q = 0; q < 4; q++) {
            float yq = y[q];
            #pragma unroll 8
            for (int src = 0; src < 32; src++) {
                float v = __shfl_sync(FULL, yq, src);
                int   j = src * 4 + q;
                a0 += v * W2[j * OUTD + o0];
                if (o1 < OUTD) a1 += v * W2[j * OUTD + o1];
            }
        }
        size_t ob = (size_t)(b0 + r) * OUTD;
        out[ob + o0] = fixv(a0);
        if (o1 < OUTD) out[ob + o1] = fixv(a1);
    }
}

extern "C" void kernel_launch(void* const* d_in, const int* in_sizes, int n_in,
                              void* d_out, int out_size)
{
    const float* history = (const float*)d_in[0];
    const float* hmask   = (const float*)d_in[1];
    const float* Wp      = (const float*)d_in[2];
    const float* bp      = (const float*)d_in[3];
    const float* Wx      = (const float*)d_in[4];
    const float* bx      = (const float*)d_in[5];
    const float* Uh      = (const float*)d_in[6];
    const float* Wd      = (const float*)d_in[7];
    const float* bd      = (const float*)d_in[8];
    const float* Wt      = (const float*)d_in[9];
    const float* bt      = (const float*)d_in[10];
    const float* ln_g    = (const float*)d_in[11];
    const float* ln_b    = (const float*)d_in[12];
    const float* W1      = (const float*)d_in[13];
    const float* b1      = (const float*)d_in[14];
    const float* W2      = (const float*)d_in[15];
    const float* b2      = (const float*)d_in[16];

    cudaFuncSetAttribute(tlstm_kernel,
                         cudaFuncAttributeMaxDynamicSharedMemorySize,
                         (int)sizeof(SM));
    tlstm_kernel<<<CTAS, THREADS, sizeof(SM)>>>(
        history, hmask, Wp, bp, Wx, bx, Uh, Wd, bd, Wt, bt,
        ln_g, ln_b, W1, b1, W2, b2, (float*)d_out);
}